// round 5
// baseline (speedup 1.0000x reference)
#include <cuda_runtime.h>
#include <cuda_bf16.h>
#include <cstdint>

#define NROWS 8192
#define DIM1  1024
#define DIM2  768
#define DOUT  256

// ---------------- scratch (static __device__ globals; no allocation) ----------------
__device__ __nv_bfloat16 g_Xb[NROWS * DIM1];
__device__ __nv_bfloat16 g_Yb[NROWS * DIM2];
__device__ __nv_bfloat16 g_Wxb[DOUT * DIM1];
__device__ __nv_bfloat16 g_Wyb[DOUT * DIM2];
__device__ __nv_bfloat16 g_Xn[NROWS * DOUT];   // bf16 normalized (for exact diag)
__device__ __nv_bfloat16 g_Yn[NROWS * DOUT];
__device__ uint8_t       g_Xq[NROWS * DOUT];   // e4m3 normalized*16 (for big GEMM)
__device__ uint8_t       g_Yq[NROWS * DOUT];
__device__ float         g_rowsum[NROWS];
__device__ float         g_colsum[NROWS];
__device__ float         g_diag[NROWS];

// ---------------- helpers ----------------
#define SWZ(x) ((x) ^ (((x) >> 3) & 0x70))

__device__ __forceinline__ void ldsm4(uint32_t& r0, uint32_t& r1, uint32_t& r2, uint32_t& r3, uint32_t a) {
    asm volatile("ldmatrix.sync.aligned.m8n8.x4.shared.b16 {%0,%1,%2,%3}, [%4];"
                 : "=r"(r0), "=r"(r1), "=r"(r2), "=r"(r3) : "r"(a));
}

__device__ __forceinline__ void mma16816(float* c, const uint32_t* a, const uint32_t* b) {
    asm volatile("mma.sync.aligned.m16n8k16.row.col.f32.bf16.bf16.f32 "
                 "{%0,%1,%2,%3},{%4,%5,%6,%7},{%8,%9},{%0,%1,%2,%3};"
                 : "+f"(c[0]), "+f"(c[1]), "+f"(c[2]), "+f"(c[3])
                 : "r"(a[0]), "r"(a[1]), "r"(a[2]), "r"(a[3]), "r"(b[0]), "r"(b[1]));
}

// fp8 e4m3 MMA, k32
__device__ __forceinline__ void mma_fp8(float* c, const uint32_t* a, const uint32_t* b) {
    asm volatile("mma.sync.aligned.m16n8k32.row.col.f32.e4m3.e4m3.f32 "
                 "{%0,%1,%2,%3},{%4,%5,%6,%7},{%8,%9},{%0,%1,%2,%3};"
                 : "+f"(c[0]), "+f"(c[1]), "+f"(c[2]), "+f"(c[3])
                 : "r"(a[0]), "r"(a[1]), "r"(a[2]), "r"(a[3]), "r"(b[0]), "r"(b[1]));
}

__device__ __forceinline__ void cpasync16(uint32_t s, const void* g) {
    asm volatile("cp.async.cg.shared.global [%0], [%1], 16;" :: "r"(s), "l"(g));
}

// ============== fused projection + row-normalize + dual-format store ==============
// Tile: 64 rows x 256 cols (full DOUT), 512 threads.
// smem per stage: A 64x64bf16 (8KB) + B 256x64bf16 (32KB) = 40KB; 2 stages = 80KB.
#define PROJ_SMEM 81920

__device__ __forceinline__ void load_chunk_proj(const __nv_bfloat16* Ag, const __nv_bfloat16* Bg,
                                                int K, uint32_t As, uint32_t Bs, int tid) {
    {
        int row = tid >> 3, col = tid & 7;
        cpasync16(As + SWZ(row * 128 + col * 16), Ag + (size_t)row * K + col * 8);
    }
#pragma unroll
    for (int i = 0; i < 4; i++) {
        int c = tid + i * 512;
        int row = c >> 3, col = c & 7;
        cpasync16(Bs + SWZ(row * 128 + col * 16), Bg + (size_t)row * K + col * 8);
    }
    asm volatile("cp.async.commit_group;" ::: "memory");
}

// WHICH==0: zero g_rowsum for this row range; WHICH==1: zero g_colsum
template <int WHICH>
__global__ void __launch_bounds__(512)
proj_norm(const __nv_bfloat16* __restrict__ A, const __nv_bfloat16* __restrict__ B,
          int K, const float* __restrict__ bias,
          __nv_bfloat16* __restrict__ Out, uint8_t* __restrict__ Qout) {
    extern __shared__ char smem[];
    const uint32_t sb = (uint32_t)__cvta_generic_to_shared(smem);

    const int tid  = threadIdx.x;
    const int lane = tid & 31;
    const int warp = tid >> 5;
    const int wm = warp >> 3;          // 0..1
    const int wn = warp & 7;           // 0..7
    const int mBase = blockIdx.x * 64;

    const __nv_bfloat16* Ab = A + (size_t)mBase * K;

    float acc[2][4][4];
#pragma unroll
    for (int i = 0; i < 2; i++)
#pragma unroll
        for (int j = 0; j < 4; j++)
#pragma unroll
            for (int q = 0; q < 4; q++) acc[i][j][q] = 0.f;

    const int KT = K >> 6;
    load_chunk_proj(Ab, B, K, sb, sb + 8192, tid);

    for (int kt = 0; kt < KT; kt++) {
        const int stage = kt & 1;
        if (kt + 1 < KT) {
            const int ns = stage ^ 1;
            load_chunk_proj(Ab + (kt + 1) * 64, B + (kt + 1) * 64, K,
                            sb + ns * 40960, sb + ns * 40960 + 8192, tid);
            asm volatile("cp.async.wait_group 1;" ::: "memory");
        } else {
            asm volatile("cp.async.wait_group 0;" ::: "memory");
        }
        __syncthreads();

        const uint32_t As = sb + stage * 40960;
        const uint32_t Bs = As + 8192;

#pragma unroll
        for (int ks = 0; ks < 4; ks++) {
            uint32_t a[2][4], b[4][2];
#pragma unroll
            for (int mt = 0; mt < 2; mt++) {
                int row = wm * 32 + mt * 16 + (lane & 15);
                int kb  = ks * 32 + ((lane >> 4) << 4);
                ldsm4(a[mt][0], a[mt][1], a[mt][2], a[mt][3], As + SWZ(row * 128 + kb));
            }
#pragma unroll
            for (int np = 0; np < 2; np++) {
                int n  = wn * 32 + np * 16 + (lane & 7) + ((lane >> 4) << 3);
                int kb = ks * 32 + (((lane >> 3) & 1) << 4);
                ldsm4(b[2 * np][0], b[2 * np][1], b[2 * np + 1][0], b[2 * np + 1][1],
                      Bs + SWZ(n * 128 + kb));
            }
#pragma unroll
            for (int mt = 0; mt < 2; mt++)
#pragma unroll
                for (int nt = 0; nt < 4; nt++)
                    mma16816(acc[mt][nt], a[mt], b[nt]);
        }
        __syncthreads();
    }

    // ---- epilogue: bias, sumsq, cross-warp reduce, scale, bf16 + fp8 store ----
    float* sred   = (float*)smem;            // [64][8]
    float* sscale = sred + 64 * 8;           // [64]

    float p[2][2] = {{0.f, 0.f}, {0.f, 0.f}};
#pragma unroll
    for (int mt = 0; mt < 2; mt++)
#pragma unroll
        for (int nt = 0; nt < 4; nt++) {
            int c = wn * 32 + nt * 8 + ((lane & 3) << 1);
            float b0 = bias[c], b1 = bias[c + 1];
            acc[mt][nt][0] += b0; acc[mt][nt][1] += b1;
            acc[mt][nt][2] += b0; acc[mt][nt][3] += b1;
            p[mt][0] += acc[mt][nt][0] * acc[mt][nt][0] + acc[mt][nt][1] * acc[mt][nt][1];
            p[mt][1] += acc[mt][nt][2] * acc[mt][nt][2] + acc[mt][nt][3] * acc[mt][nt][3];
        }
#pragma unroll
    for (int mt = 0; mt < 2; mt++)
#pragma unroll
        for (int h = 0; h < 2; h++) {
            float v = p[mt][h];
            v += __shfl_xor_sync(0xffffffffu, v, 1);
            v += __shfl_xor_sync(0xffffffffu, v, 2);
            if ((lane & 3) == 0)
                sred[(wm * 32 + mt * 16 + h * 8 + (lane >> 2)) * 8 + wn] = v;
        }
    __syncthreads();
    if (tid < 64) {
        float ss = 0.f;
#pragma unroll
        for (int i = 0; i < 8; i++) ss += sred[tid * 8 + i];
        sscale[tid] = 1.0f / fmaxf(sqrtf(ss), 1e-8f);
        if (WHICH == 0) g_rowsum[mBase + tid] = 0.f;
        else            g_colsum[mBase + tid] = 0.f;
    }
    __syncthreads();

#pragma unroll
    for (int mt = 0; mt < 2; mt++)
#pragma unroll
        for (int h = 0; h < 2; h++) {
            int r = wm * 32 + mt * 16 + h * 8 + (lane >> 2);
            float sc = sscale[r];
#pragma unroll
            for (int nt = 0; nt < 4; nt++) {
                int c = wn * 32 + nt * 8 + ((lane & 3) << 1);
                float v0 = acc[mt][nt][2 * h]     * sc;
                float v1 = acc[mt][nt][2 * h + 1] * sc;
                *(__nv_bfloat162*)(Out + (size_t)(mBase + r) * DOUT + c) =
                    __floats2bfloat162_rn(v0, v1);
                // fp8 e4m3 at 16x scale (keeps values in normal range; 1/256 folded pre-exp)
                uint16_t q;
                asm("cvt.rn.satfinite.e4m3x2.f32 %0, %1, %2;"
                    : "=h"(q) : "f"(v1 * 16.0f), "f"(v0 * 16.0f));
                *(uint16_t*)(Qout + (size_t)(mBase + r) * DOUT + c) = q;
            }
        }
}

// ================= big GEMM (fp8): 128x128 tile, 2 CTAs/SM, exp + row/col sums =======
// K = 256 fp8 bytes = two 128B chunks. smem: chunk c: A 16KB + B 16KB at c*32768. 64KB.
#define BIG_SMEM 65536

__device__ __forceinline__ void load_chunk_big(const uint8_t* Ag, const uint8_t* Bg,
                                               uint32_t As, uint32_t Bs, int tid) {
#pragma unroll
    for (int i = 0; i < 4; i++) {
        int c = tid + i * 256;
        int row = c >> 3, col = c & 7;   // 128 rows x 8 cols of 16B
        cpasync16(As + SWZ(row * 128 + col * 16), Ag + (size_t)row * DOUT + col * 16);
        cpasync16(Bs + SWZ(row * 128 + col * 16), Bg + (size_t)row * DOUT + col * 16);
    }
    asm volatile("cp.async.commit_group;" ::: "memory");
}

__global__ void __launch_bounds__(256, 2)
gemm_big(const uint8_t* __restrict__ A, const uint8_t* __restrict__ B) {
    extern __shared__ char smem[];
    const uint32_t sb = (uint32_t)__cvta_generic_to_shared(smem);

    const int tid  = threadIdx.x;
    const int lane = tid & 31;
    const int warp = tid >> 5;
    const int wmOff = (warp >> 2) * 64;   // 2 warps along M
    const int wnOff = (warp & 3) * 32;    // 4 warps along N

    const int mBase = blockIdx.y * 128;
    const int nBase = blockIdx.x * 128;

    const uint8_t* Ab = A + (size_t)mBase * DOUT;
    const uint8_t* Bb = B + (size_t)nBase * DOUT;

    float acc[4][4][4];
#pragma unroll
    for (int i = 0; i < 4; i++)
#pragma unroll
        for (int j = 0; j < 4; j++)
#pragma unroll
            for (int q = 0; q < 4; q++) acc[i][j][q] = 0.f;

    // both K-chunks issued up front
    load_chunk_big(Ab,       Bb,       sb,         sb + 16384, tid);
    load_chunk_big(Ab + 128, Bb + 128, sb + 32768, sb + 49152, tid);

#pragma unroll
    for (int kc = 0; kc < 2; kc++) {
        if (kc == 0) asm volatile("cp.async.wait_group 1;" ::: "memory");
        else         asm volatile("cp.async.wait_group 0;" ::: "memory");
        __syncthreads();

        const uint32_t As = sb + kc * 32768;
        const uint32_t Bs = As + 16384;

#pragma unroll
        for (int ks = 0; ks < 4; ks++) {     // 4 k32 steps per 128B chunk
            uint32_t a[4][4], b[4][2];
#pragma unroll
            for (int mt = 0; mt < 4; mt++) {
                int row = wmOff + mt * 16 + (lane & 15);
                int kb  = ks * 32 + ((lane >> 4) << 4);
                ldsm4(a[mt][0], a[mt][1], a[mt][2], a[mt][3], As + SWZ(row * 128 + kb));
            }
#pragma unroll
            for (int np = 0; np < 2; np++) {
                int n  = wnOff + np * 16 + (lane & 7) + ((lane >> 4) << 3);
                int kb = ks * 32 + (((lane >> 3) & 1) << 4);
                ldsm4(b[2 * np][0], b[2 * np][1], b[2 * np + 1][0], b[2 * np + 1][1],
                      Bs + SWZ(n * 128 + kb));
            }
#pragma unroll
            for (int mt = 0; mt < 4; mt++)
#pragma unroll
                for (int nt = 0; nt < 4; nt++)
                    mma_fp8(acc[mt][nt], a[mt], b[nt]);
        }
    }

    // ---- epilogue: exp(acc/256) + row/col partial sums ----
    const float ISC = 1.0f / 256.0f;   // undo 16x * 16x quantization scale

    float rp[4][2], cp[4][2];
#pragma unroll
    for (int i = 0; i < 4; i++) { rp[i][0] = rp[i][1] = 0.f; cp[i][0] = cp[i][1] = 0.f; }

#pragma unroll
    for (int mt = 0; mt < 4; mt++) {
#pragma unroll
        for (int nt = 0; nt < 4; nt++) {
            float e0 = __expf(acc[mt][nt][0] * ISC);
            float e1 = __expf(acc[mt][nt][1] * ISC);
            float e2 = __expf(acc[mt][nt][2] * ISC);
            float e3 = __expf(acc[mt][nt][3] * ISC);
            rp[mt][0] += e0 + e1;
            rp[mt][1] += e2 + e3;
            cp[nt][0] += e0 + e2;
            cp[nt][1] += e1 + e3;
        }
    }

#pragma unroll
    for (int mt = 0; mt < 4; mt++)
#pragma unroll
        for (int h = 0; h < 2; h++) {
            float v = rp[mt][h];
            v += __shfl_xor_sync(0xffffffffu, v, 1);
            v += __shfl_xor_sync(0xffffffffu, v, 2);
            if ((lane & 3) == 0)
                atomicAdd(&g_rowsum[mBase + wmOff + mt * 16 + h * 8 + (lane >> 2)], v);
        }
#pragma unroll
    for (int nt = 0; nt < 4; nt++)
#pragma unroll
        for (int j = 0; j < 2; j++) {
            float v = cp[nt][j];
            v += __shfl_xor_sync(0xffffffffu, v, 4);
            v += __shfl_xor_sync(0xffffffffu, v, 8);
            v += __shfl_xor_sync(0xffffffffu, v, 16);
            if (lane < 4)
                atomicAdd(&g_colsum[nBase + wnOff + nt * 8 + ((lane & 3) << 1) + j], v);
        }
}

// ---------------- small kernels ----------------
__global__ void conv_all(const float* __restrict__ X, const float* __restrict__ Y,
                         const float* __restrict__ Wx, const float* __restrict__ Wy) {
    const int NX = NROWS * DIM1 / 4, NY = NROWS * DIM2 / 4;
    const int NWX = DOUT * DIM1 / 4, NWY = DOUT * DIM2 / 4;
    int j = blockIdx.x * blockDim.x + threadIdx.x;
    const float* src;
    __nv_bfloat16* dst;
    if (j < NX) { src = X; dst = g_Xb; }
    else {
        j -= NX;
        if (j < NY) { src = Y; dst = g_Yb; }
        else {
            j -= NY;
            if (j < NWX) { src = Wx; dst = g_Wxb; }
            else {
                j -= NWX;
                if (j >= NWY) return;
                src = Wy; dst = g_Wyb;
            }
        }
    }
    float4 v = ((const float4*)src)[j];
    ((__nv_bfloat162*)dst)[2 * j]     = __floats2bfloat162_rn(v.x, v.y);
    ((__nv_bfloat162*)dst)[2 * j + 1] = __floats2bfloat162_rn(v.z, v.w);
}

// exact diagonal: diag[i] = Xn_i . Yn_i  (bf16 inputs, fp32 accumulate)
__global__ void diag_dot() {
    int row  = blockIdx.x * 8 + (threadIdx.x >> 5);
    int lane = threadIdx.x & 31;
    const __nv_bfloat162* x = (const __nv_bfloat162*)(g_Xn + (size_t)row * DOUT) + lane * 4;
    const __nv_bfloat162* y = (const __nv_bfloat162*)(g_Yn + (size_t)row * DOUT) + lane * 4;
    float s = 0.f;
#pragma unroll
    for (int i = 0; i < 4; i++) {
        float2 a = __bfloat1622float2(x[i]);
        float2 b = __bfloat1622float2(y[i]);
        s += a.x * b.x + a.y * b.y;
    }
#pragma unroll
    for (int o = 16; o; o >>= 1) s += __shfl_xor_sync(0xffffffffu, s, o);
    if (lane == 0) g_diag[row] = s;
}

// out[j] = log(colsum - pos) + log(rowsum - pos) - 2*diag[j],  pos = exp(diag[j])
__global__ void finalize(float* __restrict__ out) {
    int j = blockIdx.x * blockDim.x + threadIdx.x;
    if (j < NROWS) {
        float d = g_diag[j];
        float pos = __expf(d);
        out[j] = logf(g_colsum[j] - pos) + logf(g_rowsum[j] - pos) - 2.0f * d;
    }
}

// ---------------- launch ----------------
static void* sym_addr(const void* s) {
    void* p = nullptr;
    cudaGetSymbolAddress(&p, s);
    return p;
}

extern "C" void kernel_launch(void* const* d_in, const int* in_sizes, int n_in,
                              void* d_out, int out_size) {
    const float* X  = (const float*)d_in[0];
    const float* Y  = (const float*)d_in[1];
    const float* Wx = (const float*)d_in[2];
    const float* bx = (const float*)d_in[3];
    const float* Wy = (const float*)d_in[4];
    const float* by = (const float*)d_in[5];

    __nv_bfloat16* Xb  = (__nv_bfloat16*)sym_addr(g_Xb);
    __nv_bfloat16* Yb  = (__nv_bfloat16*)sym_addr(g_Yb);
    __nv_bfloat16* Wxb = (__nv_bfloat16*)sym_addr(g_Wxb);
    __nv_bfloat16* Wyb = (__nv_bfloat16*)sym_addr(g_Wyb);
    __nv_bfloat16* Xn  = (__nv_bfloat16*)sym_addr(g_Xn);
    __nv_bfloat16* Yn  = (__nv_bfloat16*)sym_addr(g_Yn);
    uint8_t*       Xq  = (uint8_t*)sym_addr(g_Xq);
    uint8_t*       Yq  = (uint8_t*)sym_addr(g_Yq);

    cudaFuncSetAttribute(proj_norm<0>, cudaFuncAttributeMaxDynamicSharedMemorySize, PROJ_SMEM);
    cudaFuncSetAttribute(proj_norm<1>, cudaFuncAttributeMaxDynamicSharedMemorySize, PROJ_SMEM);
    cudaFuncSetAttribute(gemm_big,     cudaFuncAttributeMaxDynamicSharedMemorySize, BIG_SMEM);

    // 0) conversions
    {
        const int total4 = (NROWS * DIM1 + NROWS * DIM2 + DOUT * DIM1 + DOUT * DIM2) / 4;
        conv_all<<<(total4 + 255) / 256, 256>>>(X, Y, Wx, Wy);
    }

    // 1,2) fused projection + normalize -> bf16 + fp8 (also zeroes sum accumulators)
    proj_norm<0><<<NROWS / 64, 512, PROJ_SMEM>>>(Xb, Wxb, DIM1, bx, Xn, Xq);
    proj_norm<1><<<NROWS / 64, 512, PROJ_SMEM>>>(Yb, Wyb, DIM2, by, Yn, Yq);

    // 3) big GEMM (fp8) with fused exp/rowsum/colsum
    gemm_big<<<dim3(NROWS / 128, NROWS / 128), 256, BIG_SMEM>>>(Xq, Yq);

    // 4) exact diagonal from bf16 vectors
    diag_dot<<<NROWS / 8, 256>>>();

    // 5) finalize
    finalize<<<NROWS / 256, 256>>>((float*)d_out);
}